// round 3
// baseline (speedup 1.0000x reference)
#include <cuda_runtime.h>

#define KK 16
#define LL 64
#define BB 32768
#define CHUNK 16
#define NCH (LL / CHUNK)   // 4 chunks per element

__global__ __launch_bounds__(256) void bitop_kernel(
    const float* __restrict__ op1, const float* __restrict__ op2,
    float* __restrict__ out)
{
    const int t  = blockIdx.x * 256 + threadIdx.x;
    const int e  = t >> 2;        // batch element
    const int ch = t & 3;         // digit chunk (16 digits each)

    const size_t row  = (size_t)e * (LL * KK / 4);
    const size_t coff = (size_t)ch * (CHUNK * KK / 4);
    const float4* p1 = reinterpret_cast<const float4*>(op1) + row + coff;
    const float4* p2 = reinterpret_cast<const float4*>(op2) + row + coff;
    float4* oadd = reinterpret_cast<float4*>(out)                        + row + coff;
    float4* osub = reinterpret_cast<float4*>(out + (size_t)BB * LL * KK) + row + coff;

    // ---------------- Phase A: fold chunk into affine maps st -> B + A*st ----
    float Aa = 1.f, Ba = 0.f;   // add/carry
    float As = 1.f, Bs = 0.f;   // sub/borrow

    #pragma unroll 1
    for (int l = 0; l < CHUNK; ++l) {
        const int o = l * 4;
        float4 A0 = p1[o], A1 = p1[o+1], A2 = p1[o+2], A3 = p1[o+3];
        float4 B0 = p2[o], B1 = p2[o+1], B2 = p2[o+2], B3 = p2[o+3];
        float a[16] = {A0.x,A0.y,A0.z,A0.w, A1.x,A1.y,A1.z,A1.w,
                       A2.x,A2.y,A2.z,A2.w, A3.x,A3.y,A3.z,A3.w};
        float c[16] = {B0.x,B0.y,B0.z,B0.w, B1.x,B1.y,B1.z,B1.w,
                       B2.x,B2.y,B2.z,B2.w, B3.x,B3.y,B3.z,B3.w};

        float Csuf[16];
        Csuf[15] = c[15];
        #pragma unroll
        for (int m = 14; m >= 1; --m) Csuf[m] = Csuf[m + 1] + c[m];

        float piva = 0.f, pivs = 0.f, Sa = 0.f, Ss = 0.f;
        #pragma unroll
        for (int i = 0; i < 16; ++i) {
            piva = fmaf(a[i], c[15 - i], piva);   // P(i+j == 15)
            pivs = fmaf(a[i], c[i],       pivs);  // P(i == j)
        }
        #pragma unroll
        for (int i = 1; i < 16; ++i)  Sa = fmaf(a[i], Csuf[16 - i], Sa);  // P(i+j >= 16)
        #pragma unroll
        for (int i = 0; i < 15; ++i)  Ss = fmaf(a[i], Csuf[i + 1], Ss);   // P(i <  j)

        Ba = fmaf(piva, Ba, Sa);  Aa *= piva;
        Bs = fmaf(pivs, Bs, Ss);  As *= pivs;
    }

    // ---------------- scan across the 4 chunk-lanes of this element ---------
    const int lw   = threadIdx.x & 31;
    const int base = lw & ~3;
    const int pos  = lw & 3;

    float sta = 0.f, sts = 0.f;   // incoming carry1 / borrow1 for this chunk
    #pragma unroll
    for (int k = 0; k < 3; ++k) {
        const float Ak = __shfl_sync(0xffffffffu, Aa, base + k);
        const float Bk = __shfl_sync(0xffffffffu, Ba, base + k);
        const float Sk = __shfl_sync(0xffffffffu, As, base + k);
        const float Tk = __shfl_sync(0xffffffffu, Bs, base + k);
        if (k < pos) {
            sta = fmaf(Ak, sta, Bk);
            sts = fmaf(Sk, sts, Tk);
        }
    }

    // ---------------- Phase B: full per-digit outputs (round-1 body) --------
    // software pipeline: preload digit 0 (L1/L2-hot from phase A)
    float4 A0 = p1[0], A1 = p1[1], A2 = p1[2], A3 = p1[3];
    float4 B0 = p2[0], B1 = p2[1], B2 = p2[2], B3 = p2[3];

    #pragma unroll 1
    for (int l = 0; l < CHUNK; ++l) {
        float a[16] = {A0.x,A0.y,A0.z,A0.w, A1.x,A1.y,A1.z,A1.w,
                       A2.x,A2.y,A2.z,A2.w, A3.x,A3.y,A3.z,A3.w};
        float c[16] = {B0.x,B0.y,B0.z,B0.w, B1.x,B1.y,B1.z,B1.w,
                       B2.x,B2.y,B2.z,B2.w, B3.x,B3.y,B3.z,B3.w};

        if (l < CHUNK - 1) {
            const int o = (l + 1) * 4;
            A0 = p1[o]; A1 = p1[o+1]; A2 = p1[o+2]; A3 = p1[o+3];
            B0 = p2[o]; B1 = p2[o+1]; B2 = p2[o+2]; B3 = p2[o+3];
        }

        float Qa[16], Qs[16];
        #pragma unroll
        for (int v = 0; v < 16; ++v) { Qa[v] = 0.f; Qs[v] = 0.f; }

        #pragma unroll
        for (int i = 0; i < 16; ++i) {
            #pragma unroll
            for (int j = 0; j < 16; ++j) {
                Qa[(i + j) & 15]      = fmaf(a[i], c[j], Qa[(i + j) & 15]);
                Qs[(i - j + 16) & 15] = fmaf(a[i], c[j], Qs[(i - j + 16) & 15]);
            }
        }

        float Csuf[16];
        Csuf[15] = c[15];
        #pragma unroll
        for (int m = 14; m >= 1; --m) Csuf[m] = Csuf[m + 1] + c[m];

        float Sa = 0.f, Ss = 0.f;
        #pragma unroll
        for (int i = 1; i < 16; ++i)  Sa = fmaf(a[i], Csuf[16 - i], Sa);
        #pragma unroll
        for (int i = 0; i < 15; ++i)  Ss = fmaf(a[i], Csuf[i + 1], Ss);

        float ra[16], rs[16];
        #pragma unroll
        for (int v = 0; v < 16; ++v) {
            ra[v] = fmaf(sta, Qa[(v + 15) & 15] - Qa[v], Qa[v]);
            rs[v] = fmaf(sts, Qs[(v + 1)  & 15] - Qs[v], Qs[v]);
        }

        sta = fmaf(sta, Qa[15], Sa);
        sts = fmaf(sts, Qs[0],  Ss);

        const int ob = l * 4;
        oadd[ob + 0] = make_float4(ra[0],  ra[1],  ra[2],  ra[3]);
        oadd[ob + 1] = make_float4(ra[4],  ra[5],  ra[6],  ra[7]);
        oadd[ob + 2] = make_float4(ra[8],  ra[9],  ra[10], ra[11]);
        oadd[ob + 3] = make_float4(ra[12], ra[13], ra[14], ra[15]);
        osub[ob + 0] = make_float4(rs[0],  rs[1],  rs[2],  rs[3]);
        osub[ob + 1] = make_float4(rs[4],  rs[5],  rs[6],  rs[7]);
        osub[ob + 2] = make_float4(rs[8],  rs[9],  rs[10], rs[11]);
        osub[ob + 3] = make_float4(rs[12], rs[13], rs[14], rs[15]);
    }
}

extern "C" void kernel_launch(void* const* d_in, const int* in_sizes, int n_in,
                              void* d_out, int out_size)
{
    const float* op1 = (const float*)d_in[0];
    const float* op2 = (const float*)d_in[1];
    float* out = (float*)d_out;

    bitop_kernel<<<(BB * NCH) / 256, 256>>>(op1, op2, out);
}

// round 4
// speedup vs baseline: 1.7720x; 1.7720x over previous
#include <cuda_runtime.h>

#define KK 16
#define LL 64
#define BB 32768

// Row = 64 digits * 16 floats = 256 float4 per element per tensor.
#define ROWF4 256

__global__ __launch_bounds__(128, 2) void bitop_kernel(
    const float4* __restrict__ op1, const float4* __restrict__ op2,
    float4* __restrict__ outa, float4* __restrict__ outs)
{
    // per-warp staging, rows padded to 5 float4 (80B) -> conflict-free LDS.128
    __shared__ float4 sin1[4][32][5];
    __shared__ float4 sin2[4][32][5];
    __shared__ float4 soa [4][32][5];
    __shared__ float4 sos [4][32][5];

    const int tid = threadIdx.x;
    const int w   = tid >> 5;
    const int ln  = tid & 31;
    const int ebase = blockIdx.x * 128 + w * 32;

    const int k  = ln & 3;   // float4 slot within a digit
    const int g0 = ln >> 2;  // base element index for staging

    size_t srow[4];
    #pragma unroll
    for (int r = 0; r < 4; ++r)
        srow[r] = (size_t)(ebase + g0 + 8 * r) * ROWF4;

    // prologue: stage digit 0 (coalesced: 4 lanes cover one element's 64B)
    #pragma unroll
    for (int r = 0; r < 4; ++r) {
        sin1[w][g0 + 8 * r][k] = op1[srow[r] + k];
        sin2[w][g0 + 8 * r][k] = op2[srow[r] + k];
    }
    __syncwarp();

    float sta = 0.f, sts = 0.f;   // carry1 / borrow1
    float4 pf1[4], pf2[4];

    #pragma unroll 1
    for (int l = 0; l < LL; ++l) {
        // 1. read own element's digit from smem
        float4 A0 = sin1[w][ln][0], A1 = sin1[w][ln][1],
               A2 = sin1[w][ln][2], A3 = sin1[w][ln][3];
        float4 B0 = sin2[w][ln][0], B1 = sin2[w][ln][1],
               B2 = sin2[w][ln][2], B3 = sin2[w][ln][3];
        __syncwarp();   // all lanes done reading before in-buffer is rewritten

        // 2. prefetch next digit (coalesced); latency hidden by compute below
        if (l < LL - 1) {
            const size_t off = (size_t)(l + 1) * 4 + k;
            #pragma unroll
            for (int r = 0; r < 4; ++r) {
                pf1[r] = op1[srow[r] + off];
                pf2[r] = op2[srow[r] + off];
            }
        }

        float a[16] = {A0.x,A0.y,A0.z,A0.w, A1.x,A1.y,A1.z,A1.w,
                       A2.x,A2.y,A2.z,A2.w, A3.x,A3.y,A3.z,A3.w};
        float c[16] = {B0.x,B0.y,B0.z,B0.w, B1.x,B1.y,B1.z,B1.w,
                       B2.x,B2.y,B2.z,B2.w, B3.x,B3.y,B3.z,B3.w};

        // 3. cyclic conv (add) + cyclic corr (sub)
        float Qa[16], Qs[16];
        #pragma unroll
        for (int v = 0; v < 16; ++v) { Qa[v] = 0.f; Qs[v] = 0.f; }
        #pragma unroll
        for (int i = 0; i < 16; ++i) {
            #pragma unroll
            for (int j = 0; j < 16; ++j) {
                Qa[(i + j) & 15]      = fmaf(a[i], c[j], Qa[(i + j) & 15]);
                Qs[(i - j + 16) & 15] = fmaf(a[i], c[j], Qs[(i - j + 16) & 15]);
            }
        }

        float Csuf[16];
        Csuf[15] = c[15];
        #pragma unroll
        for (int m = 14; m >= 1; --m) Csuf[m] = Csuf[m + 1] + c[m];

        float Sa = 0.f, Ss = 0.f;
        #pragma unroll
        for (int i = 1; i < 16; ++i)  Sa = fmaf(a[i], Csuf[16 - i], Sa);  // P(i+j>=16)
        #pragma unroll
        for (int i = 0; i < 15; ++i)  Ss = fmaf(a[i], Csuf[i + 1], Ss);   // P(i<j)

        float ra[16], rs[16];
        #pragma unroll
        for (int v = 0; v < 16; ++v) {
            ra[v] = fmaf(sta, Qa[(v + 15) & 15] - Qa[v], Qa[v]);
            rs[v] = fmaf(sts, Qs[(v + 1)  & 15] - Qs[v], Qs[v]);
        }
        sta = fmaf(sta, Qa[15], Sa);
        sts = fmaf(sts, Qs[0],  Ss);

        // 4. stage next digit into smem (LDG long done)
        if (l < LL - 1) {
            #pragma unroll
            for (int r = 0; r < 4; ++r) {
                sin1[w][g0 + 8 * r][k] = pf1[r];
                sin2[w][g0 + 8 * r][k] = pf2[r];
            }
        }

        // 5. results -> smem
        soa[w][ln][0] = make_float4(ra[0],  ra[1],  ra[2],  ra[3]);
        soa[w][ln][1] = make_float4(ra[4],  ra[5],  ra[6],  ra[7]);
        soa[w][ln][2] = make_float4(ra[8],  ra[9],  ra[10], ra[11]);
        soa[w][ln][3] = make_float4(ra[12], ra[13], ra[14], ra[15]);
        sos[w][ln][0] = make_float4(rs[0],  rs[1],  rs[2],  rs[3]);
        sos[w][ln][1] = make_float4(rs[4],  rs[5],  rs[6],  rs[7]);
        sos[w][ln][2] = make_float4(rs[8],  rs[9],  rs[10], rs[11]);
        sos[w][ln][3] = make_float4(rs[12], rs[13], rs[14], rs[15]);
        __syncwarp();

        // 6. coalesced stores
        const size_t off = (size_t)l * 4 + k;
        #pragma unroll
        for (int r = 0; r < 4; ++r) {
            outa[srow[r] + off] = soa[w][g0 + 8 * r][k];
            outs[srow[r] + off] = sos[w][g0 + 8 * r][k];
        }
    }
}

extern "C" void kernel_launch(void* const* d_in, const int* in_sizes, int n_in,
                              void* d_out, int out_size)
{
    const float4* op1 = (const float4*)d_in[0];
    const float4* op2 = (const float4*)d_in[1];
    float* out = (float*)d_out;
    float4* outa = (float4*)out;
    float4* outs = (float4*)(out + (size_t)BB * LL * KK);

    bitop_kernel<<<BB / 128, 128>>>(op1, op2, outa, outs);
}